// round 9
// baseline (speedup 1.0000x reference)
#include <cuda_runtime.h>
#include <cstdint>

#define VOCAB 50257
#define EMBED 256
#define HID   128
#define G4    512   // 4*HID
#define BATCH 128
#define SEQ   1024

#define LOG2E 1.4426950408889634f

// Gate-projection table: table[v][g] = sum_e emb[v][e]*W_ih[g][e] + b_ih[g]+b_hh[g]
__device__ float g_table[(size_t)VOCAB * G4];

typedef unsigned long long ull;

// ---------------- packed fp32x2 helpers ----------------
__device__ __forceinline__ ull pack2(float lo, float hi) {
    ull r; asm("mov.b64 %0, {%1, %2};" : "=l"(r) : "f"(lo), "f"(hi)); return r;
}
__device__ __forceinline__ ull splat2(float x) {
    ull r; asm("mov.b64 %0, {%1, %1};" : "=l"(r) : "f"(x)); return r;
}
__device__ __forceinline__ void unpack2(ull v, float& lo, float& hi) {
    asm("mov.b64 {%0, %1}, %2;" : "=f"(lo), "=f"(hi) : "l"(v));
}
__device__ __forceinline__ void ffma2(ull& d, ull a, ull b) {
    asm("fma.rn.f32x2 %0, %1, %2, %0;" : "+l"(d) : "l"(a), "l"(b));
}
__device__ __forceinline__ float tanhaf(float x) {
    float y; asm("tanh.approx.f32 %0, %1;" : "=f"(y) : "f"(x)); return y;
}
// packed bf16x2 (lo=even weight, hi=odd weight) -> f32x2 pair (clean mask)
__device__ __forceinline__ ull bf2pair(unsigned w) {
    unsigned lo = w << 16;
    unsigned hi = w & 0xffff0000u;
    ull r; asm("mov.b64 %0, {%1, %2};" : "=l"(r) : "r"(lo), "r"(hi));
    return r;
}
// pack two f32 into bf16x2 round-to-nearest: [bf16(whi) : bf16(wlo)]
__device__ __forceinline__ unsigned bfpack(float wlo, float whi) {
    unsigned r;
    asm("cvt.rn.bf16x2.f32 %0, %1, %2;" : "=r"(r) : "f"(whi), "f"(wlo));
    return r;
}

// =====================================================================
// Kernel 1: table[v][g] = emb[v] . W_ih[g] + bias[g]
// 128x128 tile, 256 threads, 8x8 microtile, FFMA2, pre-packed SMEM,
// ping-pong SMEM buffers (ONE barrier per k-iter) + GMEM reg prefetch.
// =====================================================================
#define TBM 128
#define TBN 128
#define TKC 16
#define ASTRIDE (TBM + 2)
#define BSTRIDE (TBN + 4)
#define NK_ITERS (EMBED / TKC)   // 16

__global__ void __launch_bounds__(256, 2) table_kernel(
    const float* __restrict__ emb,
    const float* __restrict__ W_ih,
    const float* __restrict__ b_ih,
    const float* __restrict__ b_hh)
{
    __shared__ ull   As2[2][TKC][ASTRIDE];
    __shared__ float Bs[2][TKC][BSTRIDE];

    const int v0 = blockIdx.x * TBM;
    const int g0 = blockIdx.y * TBN;
    const int tid = threadIdx.x;
    const int ty = tid >> 4;
    const int tx = tid & 15;

    const int arow = tid >> 1;
    const int acol = (tid & 1) * 8;

    ull acc[8][4];
#pragma unroll
    for (int i = 0; i < 8; i++)
#pragma unroll
        for (int p = 0; p < 4; p++) acc[i][p] = 0ull;

    const int vload = min(v0 + arow, VOCAB - 1);
    const int grow  = g0 + arow;
    const float* aptr = emb  + (size_t)vload * EMBED + acol;
    const float* bptr = W_ih + (size_t)grow  * EMBED + acol;

    float4 ra0 = *(const float4*)(aptr);
    float4 ra1 = *(const float4*)(aptr + 4);
    float4 rb0 = *(const float4*)(bptr);
    float4 rb1 = *(const float4*)(bptr + 4);

    for (int it = 0; it < NK_ITERS; it++) {
        const int pb = it & 1;
        As2[pb][acol + 0][arow] = splat2(ra0.x); As2[pb][acol + 1][arow] = splat2(ra0.y);
        As2[pb][acol + 2][arow] = splat2(ra0.z); As2[pb][acol + 3][arow] = splat2(ra0.w);
        As2[pb][acol + 4][arow] = splat2(ra1.x); As2[pb][acol + 5][arow] = splat2(ra1.y);
        As2[pb][acol + 6][arow] = splat2(ra1.z); As2[pb][acol + 7][arow] = splat2(ra1.w);
        Bs[pb][acol + 0][arow] = rb0.x; Bs[pb][acol + 1][arow] = rb0.y;
        Bs[pb][acol + 2][arow] = rb0.z; Bs[pb][acol + 3][arow] = rb0.w;
        Bs[pb][acol + 4][arow] = rb1.x; Bs[pb][acol + 5][arow] = rb1.y;
        Bs[pb][acol + 6][arow] = rb1.z; Bs[pb][acol + 7][arow] = rb1.w;
        __syncthreads();

        {
            int knext = min((it + 1) * TKC, EMBED - TKC);
            ra0 = *(const float4*)(aptr + knext);
            ra1 = *(const float4*)(aptr + knext + 4);
            rb0 = *(const float4*)(bptr + knext);
            rb1 = *(const float4*)(bptr + knext + 4);
        }

#pragma unroll
        for (int k = 0; k < TKC; k++) {
            ulonglong2 bp0 = *(const ulonglong2*)&Bs[pb][k][tx * 8];
            ulonglong2 bp1 = *(const ulonglong2*)&Bs[pb][k][tx * 8 + 4];
            ull b2[4] = { bp0.x, bp0.y, bp1.x, bp1.y };
            const ulonglong2* ap = (const ulonglong2*)&As2[pb][k][ty * 8];
            ulonglong2 a01 = ap[0], a23 = ap[1], a45 = ap[2], a67 = ap[3];
            ull av[8] = { a01.x, a01.y, a23.x, a23.y, a45.x, a45.y, a67.x, a67.y };
#pragma unroll
            for (int i = 0; i < 8; i++)
#pragma unroll
                for (int p = 0; p < 4; p++)
                    ffma2(acc[i][p], av[i], b2[p]);
        }
    }

    const int gbase = g0 + tx * 8;
    float bz[8];
#pragma unroll
    for (int c = 0; c < 8; c++) bz[c] = b_ih[gbase + c] + b_hh[gbase + c];

#pragma unroll
    for (int i = 0; i < 8; i++) {
        int v = v0 + ty * 8 + i;
        if (v < VOCAB) {
            float r[8];
#pragma unroll
            for (int p = 0; p < 4; p++) {
                float lo, hi;
                unpack2(acc[i][p], lo, hi);
                r[2 * p]     = lo + bz[2 * p];
                r[2 * p + 1] = hi + bz[2 * p + 1];
            }
            float* dst = &g_table[(size_t)v * G4 + gbase];
            *(float4*)(dst)     = make_float4(r[0], r[1], r[2], r[3]);
            *(float4*)(dst + 4) = make_float4(r[4], r[5], r[6], r[7]);
        }
    }
}

// =====================================================================
// Kernel 2: per-batch LSTM recurrence. 128 CTAs x 512 threads.
// Thread = (unit j = tid>>2, k-quarter q = tid&3).
// acc_m at lane q accumulates gate (q^m) over k in [32q,32q+32).
// ALL WEIGHTS IN REGISTERS: m=0,1 + m=2 lower half as fp32 pairs
// (40 ulls), m=2 upper half + m=3 as packed bf16x2 (24 u32s).
// -> ZERO SMEM weight traffic; crossbar carries only h broadcasts.
// Activations via single tanh.approx. One barrier per step.
// =====================================================================
#define HSKB 148   // floats per h buffer (4 slices of 36 + pad)

struct __align__(16) LstmSmem {
    float hsk[2][HSKB];       // double-buffered skewed h
    float hred[256];          // head scratch
    int   toff[SEQ + 2];      // token BYTE offsets into g_table (padded)
};

__global__ void __launch_bounds__(512, 1) lstm_kernel(
    const void* __restrict__ xraw,
    const float* __restrict__ W_hh,
    const float* __restrict__ W_fc,
    const float* __restrict__ b_fc,
    float* __restrict__ out)
{
    extern __shared__ char smem_raw[];
    LstmSmem* S = (LstmSmem*)smem_raw;

    const int b = blockIdx.x;
    const int tid = threadIdx.x;
    const int j = tid >> 2;   // hidden unit 0..127
    const int q = tid & 3;    // k-quarter 0..3

    // --- detect whether x is stored as int64 or int32 ---
    bool is64;
    {
        const int* xi = (const int*)xraw;
        int val = xi[2 * (tid & 31) + 1];
        unsigned m = __ballot_sync(0xffffffffu, val != 0);
        is64 = (m == 0u);
    }

    // --- preload token byte-offsets (tok * 2048 bytes), pad last ---
    if (is64) {
        const long long* x64 = (const long long*)xraw + (size_t)b * SEQ;
        for (int i = tid; i <= SEQ; i += 512) {
            int src = min(i, SEQ - 1);
            S->toff[i] = ((int)x64[src]) << 11;
        }
    } else {
        const int* x32 = (const int*)xraw + (size_t)b * SEQ;
        for (int i = tid; i <= SEQ; i += 512) {
            int src = min(i, SEQ - 1);
            S->toff[i] = x32[src] << 11;
        }
    }

    // --- weights, ALL in registers. acc_m holds gate (q^m). ---
    // fp32: m=0 -> wreg[0..15], m=1 -> wreg[16..31], m=2 pairs 0..7 -> wreg[32..39]
    // bf16: m=2 pairs 8..15 -> wbf[0..7], m=3 pairs 0..15 -> wbf[8..23]
    ull wreg[40];
    unsigned wbf[24];
#pragma unroll
    for (int m = 0; m < 2; m++) {
        const float4* src = (const float4*)(W_hh + (size_t)((q ^ m) * HID + j) * HID + q * 32);
#pragma unroll
        for (int u = 0; u < 8; u++) {
            float4 w = src[u];
            wreg[m * 16 + 2 * u]     = pack2(w.x, w.y);
            wreg[m * 16 + 2 * u + 1] = pack2(w.z, w.w);
        }
    }
    {   // m=2: pairs 0..7 fp32, pairs 8..15 bf16
        const float4* src = (const float4*)(W_hh + (size_t)((q ^ 2) * HID + j) * HID + q * 32);
#pragma unroll
        for (int u = 0; u < 4; u++) {
            float4 w = src[u];
            wreg[32 + 2 * u]     = pack2(w.x, w.y);
            wreg[32 + 2 * u + 1] = pack2(w.z, w.w);
        }
#pragma unroll
        for (int u = 4; u < 8; u++) {
            float4 w = src[u];
            wbf[2 * (u - 4)]     = bfpack(w.x, w.y);
            wbf[2 * (u - 4) + 1] = bfpack(w.z, w.w);
        }
    }
    {   // m=3: all 16 pairs bf16
        const float4* src = (const float4*)(W_hh + (size_t)((q ^ 3) * HID + j) * HID + q * 32);
#pragma unroll
        for (int u = 0; u < 8; u++) {
            float4 w = src[u];
            wbf[8 + 2 * u]     = bfpack(w.x, w.y);
            wbf[8 + 2 * u + 1] = bfpack(w.z, w.w);
        }
    }

    // zero both h buffers
    for (int i = tid; i < 2 * HSKB; i += 512) ((float*)S->hsk)[i] = 0.0f;

    float c = 0.0f;
    // lane q's gate: 0=i,1=f,3=o sigmoid; 2=g tanh.
    // act = sc * tanh(sc * z) + scb  (sigmoid: sc=0.5,scb=0.5; tanh: sc=1,scb=0)
    const float sc  = (q == 2) ? 1.0f : 0.5f;
    const float scb = (q == 2) ? 0.0f : 0.5f;
    const bool hwriter = (q == (j >> 5));
    const int hwidx = q * 36 + (j & 31);
    __syncthreads();

    const char* tabq = (const char*)g_table + (size_t)(q * HID + j) * 4;
    float xgq = *(const float*)(tabq + S->toff[0]);

    const float* hbase = S->hsk[0] + q * 36;

    for (int t = 0; t < SEQ; t++) {
        const ulonglong2* hp = (const ulonglong2*)(hbase + (t & 1) * HSKB);

        // prefetch next step's table entry (independent of h)
        float xg_nxt = *(const float*)(tabq + S->toff[t + 1]);

        // ---- 4 gate-partial chains, all weights from registers ----
        ull acc0 = pack2(xgq, 0.0f);
        ull acc1 = 0ull, acc2 = 0ull, acc3 = 0ull;
#pragma unroll
        for (int u = 0; u < 4; u++) {
            ulonglong2 hv0 = hp[2 * u];
            ulonglong2 hv1 = hp[2 * u + 1];
            // m=0
            ffma2(acc0, wreg[4 * u],          hv0.x);
            ffma2(acc0, wreg[4 * u + 1],      hv0.y);
            ffma2(acc0, wreg[4 * u + 2],      hv1.x);
            ffma2(acc0, wreg[4 * u + 3],      hv1.y);
            // m=1
            ffma2(acc1, wreg[16 + 4 * u],     hv0.x);
            ffma2(acc1, wreg[16 + 4 * u + 1], hv0.y);
            ffma2(acc1, wreg[16 + 4 * u + 2], hv1.x);
            ffma2(acc1, wreg[16 + 4 * u + 3], hv1.y);
            // m=2 (pairs 4u..4u+3: fp32 for u<2, bf16 regs for u>=2)
            if (u < 2) {
                ffma2(acc2, wreg[32 + 4 * u],     hv0.x);
                ffma2(acc2, wreg[32 + 4 * u + 1], hv0.y);
                ffma2(acc2, wreg[32 + 4 * u + 2], hv1.x);
                ffma2(acc2, wreg[32 + 4 * u + 3], hv1.y);
            } else {
                ffma2(acc2, bf2pair(wbf[4 * (u - 2)]),     hv0.x);
                ffma2(acc2, bf2pair(wbf[4 * (u - 2) + 1]), hv0.y);
                ffma2(acc2, bf2pair(wbf[4 * (u - 2) + 2]), hv1.x);
                ffma2(acc2, bf2pair(wbf[4 * (u - 2) + 3]), hv1.y);
            }
            // m=3 (bf16 regs)
            ffma2(acc3, bf2pair(wbf[8 + 4 * u]),     hv0.x);
            ffma2(acc3, bf2pair(wbf[8 + 4 * u + 1]), hv0.y);
            ffma2(acc3, bf2pair(wbf[8 + 4 * u + 2]), hv1.x);
            ffma2(acc3, bf2pair(wbf[8 + 4 * u + 3]), hv1.y);
        }

        float p0, p1, p2, p3, lo, hi;
        unpack2(acc0, lo, hi); p0 = lo + hi;
        unpack2(acc1, lo, hi); p1 = lo + hi;
        unpack2(acc2, lo, hi); p2 = lo + hi;
        unpack2(acc3, lo, hi); p3 = lo + hi;

        // ---- reduce: lane q ends with full z of gate q ----
        float s0 = p0 + __shfl_xor_sync(0xffffffffu, p1, 1);
        float s1 = p2 + __shfl_xor_sync(0xffffffffu, p3, 1);
        float z  = s0 + __shfl_xor_sync(0xffffffffu, s1, 2);

        // ---- activation: single tanh.approx per lane ----
        float a = fmaf(sc, tanhaf(sc * z), scb);

        // ---- gather the four activations by absolute lane (width=4) ----
        float gi_ = __shfl_sync(0xffffffffu, a, 0, 4);
        float gf_ = __shfl_sync(0xffffffffu, a, 1, 4);
        float gg_ = __shfl_sync(0xffffffffu, a, 2, 4);
        float go_ = __shfl_sync(0xffffffffu, a, 3, 4);

        // ---- cell/hidden update (identical across the 4 lanes of unit j) ----
        c = fmaf(gf_, c, gi_ * gg_);
        float h = go_ * tanhaf(c);
        if (hwriter) S->hsk[(t + 1) & 1][hwidx] = h;

        xgq = xg_nxt;
        __syncthreads();
    }

    // --- final linear head (h(SEQ) lives in buffer 0 since SEQ is even) ---
    if (tid < 256) {
        int cls = tid >> 7;
        int jj  = tid & 127;
        float hv = S->hsk[0][(jj >> 5) * 36 + (jj & 31)];
        S->hred[tid] = hv * W_fc[cls * HID + jj];
    }
    __syncthreads();
    if (tid < 2) {
        float s = b_fc[tid];
#pragma unroll 8
        for (int jj = 0; jj < HID; jj++) s += S->hred[tid * HID + jj];
        out[b * 2 + tid] = s;
    }
}

// =====================================================================
extern "C" void kernel_launch(void* const* d_in, const int* in_sizes, int n_in,
                              void* d_out, int out_size)
{
    const void*  x     = d_in[0];
    const float* emb   = (const float*)d_in[1];
    const float* W_ih  = (const float*)d_in[2];
    const float* W_hh  = (const float*)d_in[3];
    const float* b_ih  = (const float*)d_in[4];
    const float* b_hh  = (const float*)d_in[5];
    const float* W_fc  = (const float*)d_in[6];
    const float* b_fc  = (const float*)d_in[7];
    float* out = (float*)d_out;

    dim3 tgrid((VOCAB + TBM - 1) / TBM, G4 / TBN);   // 393 x 4
    table_kernel<<<tgrid, 256>>>(emb, W_ih, b_ih, b_hh);

    const int smem_bytes = (int)sizeof(LstmSmem);
    cudaFuncSetAttribute(lstm_kernel, cudaFuncAttributeMaxDynamicSharedMemorySize, smem_bytes);
    lstm_kernel<<<BATCH, 512, smem_bytes>>>(x, W_hh, W_fc, b_fc, out);
}

// round 10
// speedup vs baseline: 1.7446x; 1.7446x over previous
#include <cuda_runtime.h>
#include <cstdint>

#define VOCAB 50257
#define EMBED 256
#define HID   128
#define G4    512   // 4*HID
#define BATCH 128
#define SEQ   1024

#define LOG2E 1.4426950408889634f

// Gate-projection table: table[v][g] = sum_e emb[v][e]*W_ih[g][e] + b_ih[g]+b_hh[g]
__device__ float g_table[(size_t)VOCAB * G4];

typedef unsigned long long ull;

// ---------------- packed fp32x2 helpers ----------------
__device__ __forceinline__ ull pack2(float lo, float hi) {
    ull r; asm("mov.b64 %0, {%1, %2};" : "=l"(r) : "f"(lo), "f"(hi)); return r;
}
__device__ __forceinline__ ull splat2(float x) {
    ull r; asm("mov.b64 %0, {%1, %1};" : "=l"(r) : "f"(x)); return r;
}
__device__ __forceinline__ void unpack2(ull v, float& lo, float& hi) {
    asm("mov.b64 {%0, %1}, %2;" : "=f"(lo), "=f"(hi) : "l"(v));
}
__device__ __forceinline__ void ffma2(ull& d, ull a, ull b) {
    asm("fma.rn.f32x2 %0, %1, %2, %0;" : "+l"(d) : "l"(a), "l"(b));
}
__device__ __forceinline__ float tanhaf(float x) {
    float y; asm("tanh.approx.f32 %0, %1;" : "=f"(y) : "f"(x)); return y;
}
// packed bf16x2 (lo=even weight, hi=odd weight) -> f32x2 pair
__device__ __forceinline__ ull bf2pair(unsigned w) {
    unsigned lo = w << 16;
    unsigned hi = w & 0xffff0000u;
    ull r; asm("mov.b64 %0, {%1, %2};" : "=l"(r) : "r"(lo), "r"(hi));
    return r;
}
// pack two f32 into bf16x2 round-to-nearest: [bf16(whi) : bf16(wlo)]
__device__ __forceinline__ unsigned bfpack(float wlo, float whi) {
    unsigned r;
    asm("cvt.rn.bf16x2.f32 %0, %1, %2;" : "=r"(r) : "f"(whi), "f"(wlo));
    return r;
}

// =====================================================================
// Kernel 1: table[v][g] = emb[v] . W_ih[g] + bias[g]
// 128x128 tile, 256 threads, 8x8 microtile, FFMA2, pre-packed SMEM,
// ping-pong SMEM buffers (ONE barrier per k-iter) + DEPTH-2 GMEM
// register prefetch (2-slot ring, compile-time slots).
// =====================================================================
#define TBM 128
#define TBN 128
#define TKC 16
#define ASTRIDE (TBM + 2)
#define BSTRIDE (TBN + 4)
#define NK_ITERS (EMBED / TKC)   // 16

__global__ void __launch_bounds__(256, 2) table_kernel(
    const float* __restrict__ emb,
    const float* __restrict__ W_ih,
    const float* __restrict__ b_ih,
    const float* __restrict__ b_hh)
{
    __shared__ ull   As2[2][TKC][ASTRIDE];
    __shared__ float Bs[2][TKC][BSTRIDE];

    const int v0 = blockIdx.x * TBM;
    const int g0 = blockIdx.y * TBN;
    const int tid = threadIdx.x;
    const int ty = tid >> 4;
    const int tx = tid & 15;

    const int arow = tid >> 1;
    const int acol = (tid & 1) * 8;

    ull acc[8][4];
#pragma unroll
    for (int i = 0; i < 8; i++)
#pragma unroll
        for (int p = 0; p < 4; p++) acc[i][p] = 0ull;

    const int vload = min(v0 + arow, VOCAB - 1);
    const int grow  = g0 + arow;
    const float* aptr = emb  + (size_t)vload * EMBED + acol;
    const float* bptr = W_ih + (size_t)grow  * EMBED + acol;

    // depth-2 prefetch ring (slot = it & 1, compile-time under unroll)
    float4 ra0[2], ra1[2], rb0[2], rb1[2];
#pragma unroll
    for (int s = 0; s < 2; s++) {
        ra0[s] = *(const float4*)(aptr + s * TKC);
        ra1[s] = *(const float4*)(aptr + s * TKC + 4);
        rb0[s] = *(const float4*)(bptr + s * TKC);
        rb1[s] = *(const float4*)(bptr + s * TKC + 4);
    }

#pragma unroll 1
    for (int it2 = 0; it2 < NK_ITERS; it2 += 2) {
#pragma unroll
        for (int s = 0; s < 2; s++) {
            const int it = it2 + s;
            // store current tile (slot s) into SMEM buffer s
            As2[s][acol + 0][arow] = splat2(ra0[s].x); As2[s][acol + 1][arow] = splat2(ra0[s].y);
            As2[s][acol + 2][arow] = splat2(ra0[s].z); As2[s][acol + 3][arow] = splat2(ra0[s].w);
            As2[s][acol + 4][arow] = splat2(ra1[s].x); As2[s][acol + 5][arow] = splat2(ra1[s].y);
            As2[s][acol + 6][arow] = splat2(ra1[s].z); As2[s][acol + 7][arow] = splat2(ra1[s].w);
            Bs[s][acol + 0][arow] = rb0[s].x; Bs[s][acol + 1][arow] = rb0[s].y;
            Bs[s][acol + 2][arow] = rb0[s].z; Bs[s][acol + 3][arow] = rb0[s].w;
            Bs[s][acol + 4][arow] = rb1[s].x; Bs[s][acol + 5][arow] = rb1[s].y;
            Bs[s][acol + 6][arow] = rb1[s].z; Bs[s][acol + 7][arow] = rb1[s].w;
            __syncthreads();

            // prefetch iteration it+2 into slot s (clamped; harmless repeat)
            {
                int knext = min((it + 2) * TKC, EMBED - TKC);
                ra0[s] = *(const float4*)(aptr + knext);
                ra1[s] = *(const float4*)(aptr + knext + 4);
                rb0[s] = *(const float4*)(bptr + knext);
                rb1[s] = *(const float4*)(bptr + knext + 4);
            }

#pragma unroll
            for (int k = 0; k < TKC; k++) {
                ulonglong2 bp0 = *(const ulonglong2*)&Bs[s][k][tx * 8];
                ulonglong2 bp1 = *(const ulonglong2*)&Bs[s][k][tx * 8 + 4];
                ull b2[4] = { bp0.x, bp0.y, bp1.x, bp1.y };
                const ulonglong2* ap = (const ulonglong2*)&As2[s][k][ty * 8];
                ulonglong2 a01 = ap[0], a23 = ap[1], a45 = ap[2], a67 = ap[3];
                ull av[8] = { a01.x, a01.y, a23.x, a23.y, a45.x, a45.y, a67.x, a67.y };
#pragma unroll
                for (int i = 0; i < 8; i++)
#pragma unroll
                    for (int p = 0; p < 4; p++)
                        ffma2(acc[i][p], av[i], b2[p]);
            }
            // no trailing barrier: ping-pong; next iter's barrier protects reuse
        }
    }

    const int gbase = g0 + tx * 8;
    float bz[8];
#pragma unroll
    for (int c = 0; c < 8; c++) bz[c] = b_ih[gbase + c] + b_hh[gbase + c];

#pragma unroll
    for (int i = 0; i < 8; i++) {
        int v = v0 + ty * 8 + i;
        if (v < VOCAB) {
            float r[8];
#pragma unroll
            for (int p = 0; p < 4; p++) {
                float lo, hi;
                unpack2(acc[i][p], lo, hi);
                r[2 * p]     = lo + bz[2 * p];
                r[2 * p + 1] = hi + bz[2 * p + 1];
            }
            float* dst = &g_table[(size_t)v * G4 + gbase];
            *(float4*)(dst)     = make_float4(r[0], r[1], r[2], r[3]);
            *(float4*)(dst + 4) = make_float4(r[4], r[5], r[6], r[7]);
        }
    }
}

// =====================================================================
// Kernel 2: per-batch LSTM recurrence (R7 configuration = measured best,
// plus single-tanh activation). 128 CTAs x 512 threads.
// Thread = (unit j = tid>>2, k-quarter q = tid&3).
// acc_m at lane q accumulates gate (q^m) over k in [32q,32q+32).
// regs: m=0,1 full fp32 (32 pairs) + m=2 lower 8 pairs (40 ulls total).
// SMEM bf16x2: m=3 full (rows 0-3) + m=2 upper (rows 4-5).
// h skewed + double-buffered. One barrier per step.
// =====================================================================
#define HSKB 148   // floats per h buffer (4 slices of 36 + pad)

struct __align__(16) LstmSmem {
    uint4 wsb[6][512];        // bf16x2-packed SMEM weights, 48 KB
    float hsk[2][HSKB];       // double-buffered skewed h
    float hred[256];          // head scratch
    int   toff[SEQ + 2];      // token BYTE offsets into g_table (padded)
};

__global__ void __launch_bounds__(512, 1) lstm_kernel(
    const void* __restrict__ xraw,
    const float* __restrict__ W_hh,
    const float* __restrict__ W_fc,
    const float* __restrict__ b_fc,
    float* __restrict__ out)
{
    extern __shared__ char smem_raw[];
    LstmSmem* S = (LstmSmem*)smem_raw;

    const int b = blockIdx.x;
    const int tid = threadIdx.x;
    const int j = tid >> 2;   // hidden unit 0..127
    const int q = tid & 3;    // k-quarter 0..3

    // --- detect whether x is stored as int64 or int32 ---
    bool is64;
    {
        const int* xi = (const int*)xraw;
        int val = xi[2 * (tid & 31) + 1];
        unsigned m = __ballot_sync(0xffffffffu, val != 0);
        is64 = (m == 0u);
    }

    // --- preload token byte-offsets (tok * 2048 bytes), pad last ---
    if (is64) {
        const long long* x64 = (const long long*)xraw + (size_t)b * SEQ;
        for (int i = tid; i <= SEQ; i += 512) {
            int src = min(i, SEQ - 1);
            S->toff[i] = ((int)x64[src]) << 11;
        }
    } else {
        const int* x32 = (const int*)xraw + (size_t)b * SEQ;
        for (int i = tid; i <= SEQ; i += 512) {
            int src = min(i, SEQ - 1);
            S->toff[i] = x32[src] << 11;
        }
    }

    // --- weights. acc_m holds gate (q^m). ---
    ull wreg[40];
#pragma unroll
    for (int m = 0; m < 2; m++) {
        const float4* src = (const float4*)(W_hh + (size_t)((q ^ m) * HID + j) * HID + q * 32);
#pragma unroll
        for (int u = 0; u < 8; u++) {
            float4 w = src[u];
            wreg[m * 16 + 2 * u]     = pack2(w.x, w.y);
            wreg[m * 16 + 2 * u + 1] = pack2(w.z, w.w);
        }
    }
    {   // m=2: lower 8 pairs fp32 regs, upper 8 pairs bf16 SMEM rows 4,5
        const float4* src = (const float4*)(W_hh + (size_t)((q ^ 2) * HID + j) * HID + q * 32);
#pragma unroll
        for (int u = 0; u < 4; u++) {
            float4 w = src[u];
            wreg[32 + 2 * u]     = pack2(w.x, w.y);
            wreg[32 + 2 * u + 1] = pack2(w.z, w.w);
        }
#pragma unroll
        for (int u2 = 0; u2 < 2; u2++) {
            float4 w0 = src[4 + 2 * u2];
            float4 w1 = src[5 + 2 * u2];
            uint4 pk;
            pk.x = bfpack(w0.x, w0.y);
            pk.y = bfpack(w0.z, w0.w);
            pk.z = bfpack(w1.x, w1.y);
            pk.w = bfpack(w1.z, w1.w);
            S->wsb[4 + u2][tid] = pk;
        }
    }
    {   // m=3: all 16 pairs bf16 SMEM rows 0..3
        const float4* src = (const float4*)(W_hh + (size_t)((q ^ 3) * HID + j) * HID + q * 32);
#pragma unroll
        for (int u = 0; u < 4; u++) {
            float4 w0 = src[2 * u];
            float4 w1 = src[2 * u + 1];
            uint4 pk;
            pk.x = bfpack(w0.x, w0.y);
            pk.y = bfpack(w0.z, w0.w);
            pk.z = bfpack(w1.x, w1.y);
            pk.w = bfpack(w1.z, w1.w);
            S->wsb[u][tid] = pk;
        }
    }

    // zero both h buffers
    for (int i = tid; i < 2 * HSKB; i += 512) ((float*)S->hsk)[i] = 0.0f;

    float c = 0.0f;
    // lane q's gate: 0=i,1=f,3=o sigmoid; 2=g tanh.
    // act = sc * tanh(sc * z) + scb  (sigmoid: sc=0.5,scb=0.5; tanh: sc=1,scb=0)
    const float sc  = (q == 2) ? 1.0f : 0.5f;
    const float scb = (q == 2) ? 0.0f : 0.5f;
    const bool hwriter = (q == (j >> 5));
    const int hwidx = q * 36 + (j & 31);
    __syncthreads();

    const char* tabq = (const char*)g_table + (size_t)(q * HID + j) * 4;
    float xgq = *(const float*)(tabq + S->toff[0]);

    const float* hbase = S->hsk[0] + q * 36;
    const uint4* wsp = &S->wsb[0][tid];   // row stride = 512 uint4

    for (int t = 0; t < SEQ; t++) {
        const ulonglong2* hp = (const ulonglong2*)(hbase + (t & 1) * HSKB);

        // prefetch next step's table entry (independent of h)
        float xg_nxt = *(const float*)(tabq + S->toff[t + 1]);

        // ---- 4 gate-partial chains; xgq folded into acc0's init ----
        ull acc0 = pack2(xgq, 0.0f);
        ull acc1 = 0ull, acc2 = 0ull, acc3 = 0ull;
#pragma unroll
        for (int u = 0; u < 4; u++) {
            uint4 wv = wsp[u * 512];          // m=3 bf16 weights
            ulonglong2 hv0 = hp[2 * u];
            ulonglong2 hv1 = hp[2 * u + 1];
            ffma2(acc0, wreg[4 * u],          hv0.x);
            ffma2(acc1, wreg[16 + 4 * u],     hv0.x);
            ffma2(acc0, wreg[4 * u + 1],      hv0.y);
            ffma2(acc1, wreg[16 + 4 * u + 1], hv0.y);
            ffma2(acc0, wreg[4 * u + 2],      hv1.x);
            ffma2(acc1, wreg[16 + 4 * u + 2], hv1.x);
            ffma2(acc0, wreg[4 * u + 3],      hv1.y);
            ffma2(acc1, wreg[16 + 4 * u + 3], hv1.y);
            if (u < 2) {
                ffma2(acc2, wreg[32 + 4 * u],     hv0.x);
                ffma2(acc2, wreg[32 + 4 * u + 1], hv0.y);
                ffma2(acc2, wreg[32 + 4 * u + 2], hv1.x);
                ffma2(acc2, wreg[32 + 4 * u + 3], hv1.y);
            } else {
                uint4 wv2 = wsp[(4 + (u - 2)) * 512];
                ffma2(acc2, bf2pair(wv2.x), hv0.x);
                ffma2(acc2, bf2pair(wv2.y), hv0.y);
                ffma2(acc2, bf2pair(wv2.z), hv1.x);
                ffma2(acc2, bf2pair(wv2.w), hv1.y);
            }
            ffma2(acc3, bf2pair(wv.x), hv0.x);
            ffma2(acc3, bf2pair(wv.y), hv0.y);
            ffma2(acc3, bf2pair(wv.z), hv1.x);
            ffma2(acc3, bf2pair(wv.w), hv1.y);
        }

        float p0, p1, p2, p3, lo, hi;
        unpack2(acc0, lo, hi); p0 = lo + hi;
        unpack2(acc1, lo, hi); p1 = lo + hi;
        unpack2(acc2, lo, hi); p2 = lo + hi;
        unpack2(acc3, lo, hi); p3 = lo + hi;

        // ---- reduce: lane q ends with full z of gate q ----
        float s0 = p0 + __shfl_xor_sync(0xffffffffu, p1, 1);
        float s1 = p2 + __shfl_xor_sync(0xffffffffu, p3, 1);
        float z  = s0 + __shfl_xor_sync(0xffffffffu, s1, 2);

        // ---- activation: single tanh.approx per lane ----
        float a = fmaf(sc, tanhaf(sc * z), scb);

        // ---- gather the four activations by absolute lane (width=4) ----
        float gi_ = __shfl_sync(0xffffffffu, a, 0, 4);
        float gf_ = __shfl_sync(0xffffffffu, a, 1, 4);
        float gg_ = __shfl_sync(0xffffffffu, a, 2, 4);
        float go_ = __shfl_sync(0xffffffffu, a, 3, 4);

        // ---- cell/hidden update (identical across the 4 lanes of unit j) ----
        c = fmaf(gf_, c, gi_ * gg_);
        float h = go_ * tanhaf(c);
        if (hwriter) S->hsk[(t + 1) & 1][hwidx] = h;

        xgq = xg_nxt;
        __syncthreads();
    }

    // --- final linear head (h(SEQ) lives in buffer 0 since SEQ is even) ---
    if (tid < 256) {
        int cls = tid >> 7;
        int jj  = tid & 127;
        float hv = S->hsk[0][(jj >> 5) * 36 + (jj & 31)];
        S->hred[tid] = hv * W_fc[cls * HID + jj];
    }
    __syncthreads();
    if (tid < 2) {
        float s = b_fc[tid];
#pragma unroll 8
        for (int jj = 0; jj < HID; jj++) s += S->hred[tid * HID + jj];
        out[b * 2 + tid] = s;
    }
}

// =====================================================================
extern "C" void kernel_launch(void* const* d_in, const int* in_sizes, int n_in,
                              void* d_out, int out_size)
{
    const void*  x     = d_in[0];
    const float* emb   = (const float*)d_in[1];
    const float* W_ih  = (const float*)d_in[2];
    const float* W_hh  = (const float*)d_in[3];
    const float* b_ih  = (const float*)d_in[4];
    const float* b_hh  = (const float*)d_in[5];
    const float* W_fc  = (const float*)d_in[6];
    const float* b_fc  = (const float*)d_in[7];
    float* out = (float*)d_out;

    dim3 tgrid((VOCAB + TBM - 1) / TBM, G4 / TBN);   // 393 x 4
    table_kernel<<<tgrid, 256>>>(emb, W_ih, b_ih, b_hh);

    const int smem_bytes = (int)sizeof(LstmSmem);
    cudaFuncSetAttribute(lstm_kernel, cudaFuncAttributeMaxDynamicSharedMemorySize, smem_bytes);
    lstm_kernel<<<BATCH, 512, smem_bytes>>>(x, W_hh, W_fc, b_fc, out);
}

// round 12
// speedup vs baseline: 1.9687x; 1.1284x over previous
#include <cuda_runtime.h>
#include <cuda_bf16.h>
#include <mma.h>
#include <cstdint>

using namespace nvcuda;

#define VOCAB 50257
#define EMBED 256
#define HID   128
#define G4    512   // 4*HID
#define BATCH 128
#define SEQ   1024

// Gate-projection table: table[v][g] = sum_e emb[v][e]*W_ih[g][e] + b_ih[g]+b_hh[g]
__device__ float g_table[(size_t)VOCAB * G4];

typedef unsigned long long ull;

// ---------------- packed fp32x2 / misc helpers ----------------
__device__ __forceinline__ ull pack2(float lo, float hi) {
    ull r; asm("mov.b64 %0, {%1, %2};" : "=l"(r) : "f"(lo), "f"(hi)); return r;
}
__device__ __forceinline__ void unpack2(ull v, float& lo, float& hi) {
    asm("mov.b64 {%0, %1}, %2;" : "=f"(lo), "=f"(hi) : "l"(v));
}
__device__ __forceinline__ void ffma2(ull& d, ull a, ull b) {
    asm("fma.rn.f32x2 %0, %1, %2, %0;" : "+l"(d) : "l"(a), "l"(b));
}
__device__ __forceinline__ float tanhaf(float x) {
    float y; asm("tanh.approx.f32 %0, %1;" : "=f"(y) : "f"(x)); return y;
}
__device__ __forceinline__ ull bf2pair(unsigned w) {
    unsigned lo = w << 16;
    unsigned hi = w & 0xffff0000u;
    ull r; asm("mov.b64 %0, {%1, %2};" : "=l"(r) : "r"(lo), "r"(hi));
    return r;
}
// pack two f32 into bf16x2 round-to-nearest: [bf16(whi) : bf16(wlo)]
__device__ __forceinline__ unsigned bfpack(float wlo, float whi) {
    unsigned r;
    asm("cvt.rn.bf16x2.f32 %0, %1, %2;" : "=r"(r) : "f"(whi), "f"(wlo));
    return r;
}

// =====================================================================
// Kernel 1 (TENSOR CORES via wmma, portable compute_103):
// table[v][g] = emb[v].W_ih[g] + bias[g]
// bf16x3 error-compensated split: D = Ah@Bh + Ah@Bl + Al@Bh.
// CTA tile 128x128; 256 thr = 8 warps in 2x4 grid, warp tile 64x32.
// K chunks of 64; SMEM hi/lo bf16 tiles, row stride 72 (conflict-free).
// =====================================================================
#define CT_K 64
#define ASTR 72                 // bf16 elements per SMEM tile row
#define TILE_B (128 * ASTR * 2) // 18432 bytes per bf16 tile
#define OFF_BIAS 0
#define OFF_AH 1024
#define OFF_AL (OFF_AH + TILE_B)
#define OFF_BH (OFF_AL + TILE_B)
#define OFF_BL (OFF_BH + TILE_B)
#define TB_SMEM (OFF_BL + TILE_B)          // 74752; epilogue C reuses OFF_AH..
#define CSTR 132                // float stride of epilogue C tile

__global__ void __launch_bounds__(256) table_wmma_kernel(
    const float* __restrict__ emb,
    const float* __restrict__ W_ih,
    const float* __restrict__ b_ih,
    const float* __restrict__ b_hh)
{
    extern __shared__ char smem[];
    const int tid = threadIdx.x;
    const int wid = tid >> 5;
    const int wm = wid >> 2;        // 0..1  (vocab 64-block)
    const int wn = wid & 3;         // 0..3  (gate 32-block)
    const int v0 = blockIdx.x * 128;
    const int g0 = blockIdx.y * 128;

    if (tid < 128)
        ((float*)(smem + OFF_BIAS))[tid] = b_ih[g0 + tid] + b_hh[g0 + tid];

    __nv_bfloat16* Ah = (__nv_bfloat16*)(smem + OFF_AH);
    __nv_bfloat16* Al = (__nv_bfloat16*)(smem + OFF_AL);
    __nv_bfloat16* Bh = (__nv_bfloat16*)(smem + OFF_BH);
    __nv_bfloat16* Bl = (__nv_bfloat16*)(smem + OFF_BL);

    wmma::fragment<wmma::accumulator, 16, 16, 16, float> acc[4][2];
#pragma unroll
    for (int i = 0; i < 4; i++)
#pragma unroll
        for (int jj = 0; jj < 2; jj++)
            wmma::fill_fragment(acc[i][jj], 0.0f);

    // loader mapping: row r = tid>>1 (0..127), col block = (tid&1)*32
    const int lr = tid >> 1;
    const int lcb = (tid & 1) * 32;
    const int vrow = min(v0 + lr, VOCAB - 1);
    const float* asrc = emb  + (size_t)vrow * EMBED + lcb;
    const float* bsrc = W_ih + (size_t)(g0 + lr) * EMBED + lcb;

    for (int c = 0; c < EMBED / CT_K; c++) {
        // ---- convert fp32 -> bf16 hi + residual lo, into SMEM tiles ----
#pragma unroll
        for (int f = 0; f < 8; f++) {
            const int col = lcb + 4 * f;            // within chunk
            const int eo = lr * ASTR + col;         // element offset in tile
            {
                float4 a = *(const float4*)(asrc + c * CT_K + 4 * f);
                unsigned h01 = bfpack(a.x, a.y);
                unsigned h23 = bfpack(a.z, a.w);
                unsigned l01 = bfpack(a.x - __uint_as_float(h01 << 16),
                                      a.y - __uint_as_float(h01 & 0xffff0000u));
                unsigned l23 = bfpack(a.z - __uint_as_float(h23 << 16),
                                      a.w - __uint_as_float(h23 & 0xffff0000u));
                *(uint2*)((char*)Ah + eo * 2) = make_uint2(h01, h23);
                *(uint2*)((char*)Al + eo * 2) = make_uint2(l01, l23);
            }
            {
                float4 b = *(const float4*)(bsrc + c * CT_K + 4 * f);
                unsigned h01 = bfpack(b.x, b.y);
                unsigned h23 = bfpack(b.z, b.w);
                unsigned l01 = bfpack(b.x - __uint_as_float(h01 << 16),
                                      b.y - __uint_as_float(h01 & 0xffff0000u));
                unsigned l23 = bfpack(b.z - __uint_as_float(h23 << 16),
                                      b.w - __uint_as_float(h23 & 0xffff0000u));
                *(uint2*)((char*)Bh + eo * 2) = make_uint2(h01, h23);
                *(uint2*)((char*)Bl + eo * 2) = make_uint2(l01, l23);
            }
        }
        __syncthreads();

        // ---- 4 k-steps of m16n16k16, x3 split ----
#pragma unroll
        for (int ks = 0; ks < 4; ks++) {
            const int k0 = ks * 16;
            wmma::fragment<wmma::matrix_b, 16, 16, 16, __nv_bfloat16, wmma::col_major> fBh[2], fBl[2];
#pragma unroll
            for (int jj = 0; jj < 2; jj++) {
                const int gg = (wn * 32 + jj * 16) * ASTR + k0;
                wmma::load_matrix_sync(fBh[jj], Bh + gg, ASTR);
                wmma::load_matrix_sync(fBl[jj], Bl + gg, ASTR);
            }
#pragma unroll
            for (int i = 0; i < 4; i++) {
                const int vv = (wm * 64 + i * 16) * ASTR + k0;
                wmma::fragment<wmma::matrix_a, 16, 16, 16, __nv_bfloat16, wmma::row_major> fAh, fAl;
                wmma::load_matrix_sync(fAh, Ah + vv, ASTR);
                wmma::load_matrix_sync(fAl, Al + vv, ASTR);
#pragma unroll
                for (int jj = 0; jj < 2; jj++) {
                    wmma::mma_sync(acc[i][jj], fAh, fBh[jj], acc[i][jj]);
                    wmma::mma_sync(acc[i][jj], fAh, fBl[jj], acc[i][jj]);
                    wmma::mma_sync(acc[i][jj], fAl, fBh[jj], acc[i][jj]);
                }
            }
        }
        __syncthreads();   // before SMEM tiles are overwritten (or reused by epilogue)
    }

    // ---- epilogue: accs -> SMEM C (reuses tile region), bias add, store ----
    float* C = (float*)(smem + OFF_AH);
#pragma unroll
    for (int i = 0; i < 4; i++)
#pragma unroll
        for (int jj = 0; jj < 2; jj++)
            wmma::store_matrix_sync(C + (wm * 64 + i * 16) * CSTR + wn * 32 + jj * 16,
                                    acc[i][jj], CSTR, wmma::mem_row_major);
    __syncthreads();

    {
        const int r = tid >> 1;
        const int cb = (tid & 1) * 64;
        const int v = v0 + r;
        if (v < VOCAB) {
            const float* Sb = (const float*)(smem + OFF_BIAS);
            float* dst = g_table + (size_t)v * G4 + g0 + cb;
            const float* src = C + r * CSTR + cb;
#pragma unroll
            for (int f = 0; f < 16; f++) {
                float4 o = *(const float4*)(src + 4 * f);
                o.x += Sb[cb + 4 * f + 0];
                o.y += Sb[cb + 4 * f + 1];
                o.z += Sb[cb + 4 * f + 2];
                o.w += Sb[cb + 4 * f + 3];
                *(float4*)(dst + 4 * f) = o;
            }
        }
    }
}

// =====================================================================
// Kernel 2: per-batch LSTM recurrence (measured-best R7/R10 config).
// 128 CTAs x 512 threads. Thread = (unit j = tid>>2, quarter q = tid&3).
// regs: m=0,1 full fp32 + m=2 lower 8 pairs. SMEM bf16x2: m=3 + m=2 upper.
// h skewed + double-buffered; single tanh.approx; one barrier per step.
// =====================================================================
#define HSKB 148

struct __align__(16) LstmSmem {
    uint4 wsb[6][512];
    float hsk[2][HSKB];
    float hred[256];
    int   toff[SEQ + 2];
};

__global__ void __launch_bounds__(512, 1) lstm_kernel(
    const void* __restrict__ xraw,
    const float* __restrict__ W_hh,
    const float* __restrict__ W_fc,
    const float* __restrict__ b_fc,
    float* __restrict__ out)
{
    extern __shared__ char smem_raw[];
    LstmSmem* S = (LstmSmem*)smem_raw;

    const int b = blockIdx.x;
    const int tid = threadIdx.x;
    const int j = tid >> 2;
    const int q = tid & 3;

    bool is64;
    {
        const int* xi = (const int*)xraw;
        int val = xi[2 * (tid & 31) + 1];
        unsigned m = __ballot_sync(0xffffffffu, val != 0);
        is64 = (m == 0u);
    }

    if (is64) {
        const long long* x64 = (const long long*)xraw + (size_t)b * SEQ;
        for (int i = tid; i <= SEQ; i += 512) {
            int src = min(i, SEQ - 1);
            S->toff[i] = ((int)x64[src]) << 11;
        }
    } else {
        const int* x32 = (const int*)xraw + (size_t)b * SEQ;
        for (int i = tid; i <= SEQ; i += 512) {
            int src = min(i, SEQ - 1);
            S->toff[i] = x32[src] << 11;
        }
    }

    ull wreg[40];
#pragma unroll
    for (int m = 0; m < 2; m++) {
        const float4* src = (const float4*)(W_hh + (size_t)((q ^ m) * HID + j) * HID + q * 32);
#pragma unroll
        for (int u = 0; u < 8; u++) {
            float4 w = src[u];
            wreg[m * 16 + 2 * u]     = pack2(w.x, w.y);
            wreg[m * 16 + 2 * u + 1] = pack2(w.z, w.w);
        }
    }
    {
        const float4* src = (const float4*)(W_hh + (size_t)((q ^ 2) * HID + j) * HID + q * 32);
#pragma unroll
        for (int u = 0; u < 4; u++) {
            float4 w = src[u];
            wreg[32 + 2 * u]     = pack2(w.x, w.y);
            wreg[32 + 2 * u + 1] = pack2(w.z, w.w);
        }
#pragma unroll
        for (int u2 = 0; u2 < 2; u2++) {
            float4 w0 = src[4 + 2 * u2];
            float4 w1 = src[5 + 2 * u2];
            uint4 pk;
            pk.x = bfpack(w0.x, w0.y);
            pk.y = bfpack(w0.z, w0.w);
            pk.z = bfpack(w1.x, w1.y);
            pk.w = bfpack(w1.z, w1.w);
            S->wsb[4 + u2][tid] = pk;
        }
    }
    {
        const float4* src = (const float4*)(W_hh + (size_t)((q ^ 3) * HID + j) * HID + q * 32);
#pragma unroll
        for (int u = 0; u < 4; u++) {
            float4 w0 = src[2 * u];
            float4 w1 = src[2 * u + 1];
            uint4 pk;
            pk.x = bfpack(w0.x, w0.y);
            pk.y = bfpack(w0.z, w0.w);
            pk.z = bfpack(w1.x, w1.y);
            pk.w = bfpack(w1.z, w1.w);
            S->wsb[u][tid] = pk;
        }
    }

    for (int i = tid; i < 2 * HSKB; i += 512) ((float*)S->hsk)[i] = 0.0f;

    float c = 0.0f;
    const float sc  = (q == 2) ? 1.0f : 0.5f;
    const float scb = (q == 2) ? 0.0f : 0.5f;
    const bool hwriter = (q == (j >> 5));
    const int hwidx = q * 36 + (j & 31);
    __syncthreads();

    const char* tabq = (const char*)g_table + (size_t)(q * HID + j) * 4;
    float xgq = *(const float*)(tabq + S->toff[0]);

    const float* hbase = S->hsk[0] + q * 36;
    const uint4* wsp = &S->wsb[0][tid];

    for (int t = 0; t < SEQ; t++) {
        const ulonglong2* hp = (const ulonglong2*)(hbase + (t & 1) * HSKB);
        float xg_nxt = *(const float*)(tabq + S->toff[t + 1]);

        ull acc0 = pack2(xgq, 0.0f);
        ull acc1 = 0ull, acc2 = 0ull, acc3 = 0ull;
#pragma unroll
        for (int u = 0; u < 4; u++) {
            uint4 wv = wsp[u * 512];
            ulonglong2 hv0 = hp[2 * u];
            ulonglong2 hv1 = hp[2 * u + 1];
            ffma2(acc0, wreg[4 * u],          hv0.x);
            ffma2(acc1, wreg[16 + 4 * u],     hv0.x);
            ffma2(acc0, wreg[4 * u + 1],      hv0.y);
            ffma2(acc1, wreg[16 + 4 * u + 1], hv0.y);
            ffma2(acc0, wreg[4 * u + 2],      hv1.x);
            ffma2(acc1, wreg[16 + 4 * u + 2], hv1.x);
            ffma2(acc0, wreg[4 * u + 3],      hv1.y);
            ffma2(acc1, wreg[16 + 4 * u + 3], hv1.y);
            if (u < 2) {
                ffma2(acc2, wreg[32 + 4 * u],     hv0.x);
                ffma2(acc2, wreg[32 + 4 * u + 1], hv0.y);
                ffma2(acc2, wreg[32 + 4 * u + 2], hv1.x);
                ffma2(acc2, wreg[32 + 4 * u + 3], hv1.y);
            } else {
                uint4 wv2 = wsp[(4 + (u - 2)) * 512];
                ffma2(acc2, bf2pair(wv2.x), hv0.x);
                ffma2(acc2, bf2pair(wv2.y), hv0.y);
                ffma2(acc2, bf2pair(wv2.z), hv1.x);
                ffma2(acc2, bf2pair(wv2.w), hv1.y);
            }
            ffma2(acc3, bf2pair(wv.x), hv0.x);
            ffma2(acc3, bf2pair(wv.y), hv0.y);
            ffma2(acc3, bf2pair(wv.z), hv1.x);
            ffma2(acc3, bf2pair(wv.w), hv1.y);
        }

        float p0, p1, p2, p3, lo, hi;
        unpack2(acc0, lo, hi); p0 = lo + hi;
        unpack2(acc1, lo, hi); p1 = lo + hi;
        unpack2(acc2, lo, hi); p2 = lo + hi;
        unpack2(acc3, lo, hi); p3 = lo + hi;

        float s0 = p0 + __shfl_xor_sync(0xffffffffu, p1, 1);
        float s1 = p2 + __shfl_xor_sync(0xffffffffu, p3, 1);
        float z  = s0 + __shfl_xor_sync(0xffffffffu, s1, 2);

        float a = fmaf(sc, tanhaf(sc * z), scb);

        float gi_ = __shfl_sync(0xffffffffu, a, 0, 4);
        float gf_ = __shfl_sync(0xffffffffu, a, 1, 4);
        float gg_ = __shfl_sync(0xffffffffu, a, 2, 4);
        float go_ = __shfl_sync(0xffffffffu, a, 3, 4);

        c = fmaf(gf_, c, gi_ * gg_);
        float h = go_ * tanhaf(c);
        if (hwriter) S->hsk[(t + 1) & 1][hwidx] = h;

        xgq = xg_nxt;
        __syncthreads();
    }

    if (tid < 256) {
        int cls = tid >> 7;
        int jj  = tid & 127;
        float hv = S->hsk[0][(jj >> 5) * 36 + (jj & 31)];
        S->hred[tid] = hv * W_fc[cls * HID + jj];
    }
    __syncthreads();
    if (tid < 2) {
        float s = b_fc[tid];
#pragma unroll 8
        for (int jj = 0; jj < HID; jj++) s += S->hred[tid * HID + jj];
        out[b * 2 + tid] = s;
    }
}

// =====================================================================
extern "C" void kernel_launch(void* const* d_in, const int* in_sizes, int n_in,
                              void* d_out, int out_size)
{
    const void*  x     = d_in[0];
    const float* emb   = (const float*)d_in[1];
    const float* W_ih  = (const float*)d_in[2];
    const float* W_hh  = (const float*)d_in[3];
    const float* b_ih  = (const float*)d_in[4];
    const float* b_hh  = (const float*)d_in[5];
    const float* W_fc  = (const float*)d_in[6];
    const float* b_fc  = (const float*)d_in[7];
    float* out = (float*)d_out;

    cudaFuncSetAttribute(table_wmma_kernel, cudaFuncAttributeMaxDynamicSharedMemorySize, TB_SMEM);
    dim3 tgrid((VOCAB + 127) / 128, G4 / 128);   // 393 x 4
    table_wmma_kernel<<<tgrid, 256, TB_SMEM>>>(emb, W_ih, b_ih, b_hh);

    const int smem_bytes = (int)sizeof(LstmSmem);
    cudaFuncSetAttribute(lstm_kernel, cudaFuncAttributeMaxDynamicSharedMemorySize, smem_bytes);
    lstm_kernel<<<BATCH, 512, smem_bytes>>>(x, W_hh, W_fc, b_fc, out);
}

// round 13
// speedup vs baseline: 2.0864x; 1.0598x over previous
#include <cuda_runtime.h>
#include <cuda_bf16.h>
#include <mma.h>
#include <cstdint>

using namespace nvcuda;

#define VOCAB 50257
#define EMBED 256
#define HID   128
#define G4    512   // 4*HID
#define BATCH 128
#define SEQ   1024

// Gate-projection table: table[v][g] = sum_e emb[v][e]*W_ih[g][e] + b_ih[g]+b_hh[g]
__device__ float g_table[(size_t)VOCAB * G4];
// pre-converted bf16 hi/lo copies (split: x = hi + lo, lo = residual)
__device__ __nv_bfloat16 g_embh[(size_t)VOCAB * EMBED];
__device__ __nv_bfloat16 g_embl[(size_t)VOCAB * EMBED];
__device__ __nv_bfloat16 g_wih_h[(size_t)G4 * EMBED];
__device__ __nv_bfloat16 g_wih_l[(size_t)G4 * EMBED];

typedef unsigned long long ull;

// ---------------- helpers ----------------
__device__ __forceinline__ ull pack2(float lo, float hi) {
    ull r; asm("mov.b64 %0, {%1, %2};" : "=l"(r) : "f"(lo), "f"(hi)); return r;
}
__device__ __forceinline__ void unpack2(ull v, float& lo, float& hi) {
    asm("mov.b64 {%0, %1}, %2;" : "=f"(lo), "=f"(hi) : "l"(v));
}
__device__ __forceinline__ void ffma2(ull& d, ull a, ull b) {
    asm("fma.rn.f32x2 %0, %1, %2, %0;" : "+l"(d) : "l"(a), "l"(b));
}
__device__ __forceinline__ float tanhaf(float x) {
    float y; asm("tanh.approx.f32 %0, %1;" : "=f"(y) : "f"(x)); return y;
}
__device__ __forceinline__ ull bf2pair(unsigned w) {
    unsigned lo = w << 16;
    unsigned hi = w & 0xffff0000u;
    ull r; asm("mov.b64 %0, {%1, %2};" : "=l"(r) : "r"(lo), "r"(hi));
    return r;
}
__device__ __forceinline__ unsigned bfpack(float wlo, float whi) {
    unsigned r;
    asm("cvt.rn.bf16x2.f32 %0, %1, %2;" : "=r"(r) : "f"(whi), "f"(wlo));
    return r;
}

// =====================================================================
// Kernel 0: fp32 -> bf16 hi + residual-lo split (run once per tensor)
// =====================================================================
__global__ void __launch_bounds__(256) conv_split_kernel(
    const float* __restrict__ src,
    __nv_bfloat16* __restrict__ dsth,
    __nv_bfloat16* __restrict__ dstl,
    int n4)
{
    int i = blockIdx.x * 256 + threadIdx.x;
    int stride = gridDim.x * 256;
    for (; i < n4; i += stride) {
        float4 a = ((const float4*)src)[i];
        unsigned h01 = bfpack(a.x, a.y);
        unsigned h23 = bfpack(a.z, a.w);
        unsigned l01 = bfpack(a.x - __uint_as_float(h01 << 16),
                              a.y - __uint_as_float(h01 & 0xffff0000u));
        unsigned l23 = bfpack(a.z - __uint_as_float(h23 << 16),
                              a.w - __uint_as_float(h23 & 0xffff0000u));
        ((uint2*)dsth)[i] = make_uint2(h01, h23);
        ((uint2*)dstl)[i] = make_uint2(l01, l23);
    }
}

// =====================================================================
// Kernel 1 (tensor cores, wmma): table = emb @ W_ih^T + bias
// bf16x3 split: D = Ah@Bh + Ah@Bl + Al@Bh, inputs pre-converted.
// CTA tile 128x128, 256 thr (8 warps, 2x4), warp tile 64x32.
// 2 CTAs/SM to overlap loads of one CTA with MMA of the other.
// =====================================================================
#define CT_K 64
#define ASTR 72                 // bf16 per SMEM tile row (stride)
#define TILE_B (128 * ASTR * 2) // 18432 B per tile
#define OFF_BIAS 0
#define OFF_AH 1024
#define OFF_AL (OFF_AH + TILE_B)
#define OFF_BH (OFF_AL + TILE_B)
#define OFF_BL (OFF_BH + TILE_B)
#define TB_SMEM (OFF_BL + TILE_B)   // 74752 B
#define CSTR 132

__global__ void __launch_bounds__(256, 2) table_wmma_kernel(
    const float* __restrict__ b_ih,
    const float* __restrict__ b_hh)
{
    extern __shared__ char smem[];
    const int tid = threadIdx.x;
    const int wid = tid >> 5;
    const int wm = wid >> 2;        // 0..1  (vocab 64-block)
    const int wn = wid & 3;         // 0..3  (gate 32-block)
    const int v0 = blockIdx.x * 128;
    const int g0 = blockIdx.y * 128;

    if (tid < 128)
        ((float*)(smem + OFF_BIAS))[tid] = b_ih[g0 + tid] + b_hh[g0 + tid];

    __nv_bfloat16* Ah = (__nv_bfloat16*)(smem + OFF_AH);
    __nv_bfloat16* Al = (__nv_bfloat16*)(smem + OFF_AL);
    __nv_bfloat16* Bh = (__nv_bfloat16*)(smem + OFF_BH);
    __nv_bfloat16* Bl = (__nv_bfloat16*)(smem + OFF_BL);

    wmma::fragment<wmma::accumulator, 16, 16, 16, float> acc[4][2];
#pragma unroll
    for (int i = 0; i < 4; i++)
#pragma unroll
        for (int jj = 0; jj < 2; jj++)
            wmma::fill_fragment(acc[i][jj], 0.0f);

    // loader mapping: row = tid>>1 (0..127), col half = (tid&1)*32
    const int lr = tid >> 1;
    const int lch = (tid & 1) * 32;     // bf16 col offset within 64-chunk
    const int vrow = min(v0 + lr, VOCAB - 1);
    const size_t aoff = (size_t)vrow * EMBED + lch;
    const size_t boff = (size_t)(g0 + lr) * EMBED + lch;
    // SMEM dst byte offset for this thread's 32 bf16
    const int dso = lr * (ASTR * 2) + lch * 2;

    for (int c = 0; c < EMBED / CT_K; c++) {
        const size_t ko = (size_t)c * CT_K;
#pragma unroll
        for (int i = 0; i < 4; i++) {
            ((uint4*)((char*)Ah + dso))[i] = ((const uint4*)(g_embh  + aoff + ko))[i];
            ((uint4*)((char*)Al + dso))[i] = ((const uint4*)(g_embl  + aoff + ko))[i];
            ((uint4*)((char*)Bh + dso))[i] = ((const uint4*)(g_wih_h + boff + ko))[i];
            ((uint4*)((char*)Bl + dso))[i] = ((const uint4*)(g_wih_l + boff + ko))[i];
        }
        __syncthreads();

#pragma unroll
        for (int ks = 0; ks < 4; ks++) {
            const int k0 = ks * 16;
            wmma::fragment<wmma::matrix_b, 16, 16, 16, __nv_bfloat16, wmma::col_major> fBh[2], fBl[2];
#pragma unroll
            for (int jj = 0; jj < 2; jj++) {
                const int gg = (wn * 32 + jj * 16) * ASTR + k0;
                wmma::load_matrix_sync(fBh[jj], Bh + gg, ASTR);
                wmma::load_matrix_sync(fBl[jj], Bl + gg, ASTR);
            }
#pragma unroll
            for (int i = 0; i < 4; i++) {
                const int vv = (wm * 64 + i * 16) * ASTR + k0;
                wmma::fragment<wmma::matrix_a, 16, 16, 16, __nv_bfloat16, wmma::row_major> fAh, fAl;
                wmma::load_matrix_sync(fAh, Ah + vv, ASTR);
                wmma::load_matrix_sync(fAl, Al + vv, ASTR);
#pragma unroll
                for (int jj = 0; jj < 2; jj++) {
                    wmma::mma_sync(acc[i][jj], fAh, fBh[jj], acc[i][jj]);
                    wmma::mma_sync(acc[i][jj], fAh, fBl[jj], acc[i][jj]);
                    wmma::mma_sync(acc[i][jj], fAl, fBh[jj], acc[i][jj]);
                }
            }
        }
        __syncthreads();
    }

    // ---- epilogue: accs -> SMEM C (reuse tile region), bias add, store ----
    float* C = (float*)(smem + OFF_AH);
#pragma unroll
    for (int i = 0; i < 4; i++)
#pragma unroll
        for (int jj = 0; jj < 2; jj++)
            wmma::store_matrix_sync(C + (wm * 64 + i * 16) * CSTR + wn * 32 + jj * 16,
                                    acc[i][jj], CSTR, wmma::mem_row_major);
    __syncthreads();

    {
        const int r = tid >> 1;
        const int cb = (tid & 1) * 64;
        const int v = v0 + r;
        if (v < VOCAB) {
            const float* Sb = (const float*)(smem + OFF_BIAS);
            float* dst = g_table + (size_t)v * G4 + g0 + cb;
            const float* src = C + r * CSTR + cb;
#pragma unroll
            for (int f = 0; f < 16; f++) {
                float4 o = *(const float4*)(src + 4 * f);
                o.x += Sb[cb + 4 * f + 0];
                o.y += Sb[cb + 4 * f + 1];
                o.z += Sb[cb + 4 * f + 2];
                o.w += Sb[cb + 4 * f + 3];
                *(float4*)(dst + 4 * f) = o;
            }
        }
    }
}

// =====================================================================
// Kernel 2: per-batch LSTM recurrence (measured-best config, FROZEN).
// =====================================================================
#define HSKB 148

struct __align__(16) LstmSmem {
    uint4 wsb[6][512];
    float hsk[2][HSKB];
    float hred[256];
    int   toff[SEQ + 2];
};

__global__ void __launch_bounds__(512, 1) lstm_kernel(
    const void* __restrict__ xraw,
    const float* __restrict__ W_hh,
    const float* __restrict__ W_fc,
    const float* __restrict__ b_fc,
    float* __restrict__ out)
{
    extern __shared__ char smem_raw[];
    LstmSmem* S = (LstmSmem*)smem_raw;

    const int b = blockIdx.x;
    const int tid = threadIdx.x;
    const int j = tid >> 2;
    const int q = tid & 3;

    bool is64;
    {
        const int* xi = (const int*)xraw;
        int val = xi[2 * (tid & 31) + 1];
        unsigned m = __ballot_sync(0xffffffffu, val != 0);
        is64 = (m == 0u);
    }

    if (is64) {
        const long long* x64 = (const long long*)xraw + (size_t)b * SEQ;
        for (int i = tid; i <= SEQ; i += 512) {
            int src = min(i, SEQ - 1);
            S->toff[i] = ((int)x64[src]) << 11;
        }
    } else {
        const int* x32 = (const int*)xraw + (size_t)b * SEQ;
        for (int i = tid; i <= SEQ; i += 512) {
            int src = min(i, SEQ - 1);
            S->toff[i] = x32[src] << 11;
        }
    }

    ull wreg[40];
#pragma unroll
    for (int m = 0; m < 2; m++) {
        const float4* src = (const float4*)(W_hh + (size_t)((q ^ m) * HID + j) * HID + q * 32);
#pragma unroll
        for (int u = 0; u < 8; u++) {
            float4 w = src[u];
            wreg[m * 16 + 2 * u]     = pack2(w.x, w.y);
            wreg[m * 16 + 2 * u + 1] = pack2(w.z, w.w);
        }
    }
    {
        const float4* src = (const float4*)(W_hh + (size_t)((q ^ 2) * HID + j) * HID + q * 32);
#pragma unroll
        for (int u = 0; u < 4; u++) {
            float4 w = src[u];
            wreg[32 + 2 * u]     = pack2(w.x, w.y);
            wreg[32 + 2 * u + 1] = pack2(w.z, w.w);
        }
#pragma unroll
        for (int u2 = 0; u2 < 2; u2++) {
            float4 w0 = src[4 + 2 * u2];
            float4 w1 = src[5 + 2 * u2];
            uint4 pk;
            pk.x = bfpack(w0.x, w0.y);
            pk.y = bfpack(w0.z, w0.w);
            pk.z = bfpack(w1.x, w1.y);
            pk.w = bfpack(w1.z, w1.w);
            S->wsb[4 + u2][tid] = pk;
        }
    }
    {
        const float4* src = (const float4*)(W_hh + (size_t)((q ^ 3) * HID + j) * HID + q * 32);
#pragma unroll
        for (int u = 0; u < 4; u++) {
            float4 w0 = src[2 * u];
            float4 w1 = src[2 * u + 1];
            uint4 pk;
            pk.x = bfpack(w0.x, w0.y);
            pk.y = bfpack(w0.z, w0.w);
            pk.z = bfpack(w1.x, w1.y);
            pk.w = bfpack(w1.z, w1.w);
            S->wsb[u][tid] = pk;
        }
    }

    for (int i = tid; i < 2 * HSKB; i += 512) ((float*)S->hsk)[i] = 0.0f;

    float c = 0.0f;
    const float sc  = (q == 2) ? 1.0f : 0.5f;
    const float scb = (q == 2) ? 0.0f : 0.5f;
    const bool hwriter = (q == (j >> 5));
    const int hwidx = q * 36 + (j & 31);
    __syncthreads();

    const char* tabq = (const char*)g_table + (size_t)(q * HID + j) * 4;
    float xgq = *(const float*)(tabq + S->toff[0]);

    const float* hbase = S->hsk[0] + q * 36;
    const uint4* wsp = &S->wsb[0][tid];

    for (int t = 0; t < SEQ; t++) {
        const ulonglong2* hp = (const ulonglong2*)(hbase + (t & 1) * HSKB);
        float xg_nxt = *(const float*)(tabq + S->toff[t + 1]);

        ull acc0 = pack2(xgq, 0.0f);
        ull acc1 = 0ull, acc2 = 0ull, acc3 = 0ull;
#pragma unroll
        for (int u = 0; u < 4; u++) {
            uint4 wv = wsp[u * 512];
            ulonglong2 hv0 = hp[2 * u];
            ulonglong2 hv1 = hp[2 * u + 1];
            ffma2(acc0, wreg[4 * u],          hv0.x);
            ffma2(acc1, wreg[16 + 4 * u],     hv0.x);
            ffma2(acc0, wreg[4 * u + 1],      hv0.y);
            ffma2(acc1, wreg[16 + 4 * u + 1], hv0.y);
            ffma2(acc0, wreg[4 * u + 2],      hv1.x);
            ffma2(acc1, wreg[16 + 4 * u + 2], hv1.x);
            ffma2(acc0, wreg[4 * u + 3],      hv1.y);
            ffma2(acc1, wreg[16 + 4 * u + 3], hv1.y);
            if (u < 2) {
                ffma2(acc2, wreg[32 + 4 * u],     hv0.x);
                ffma2(acc2, wreg[32 + 4 * u + 1], hv0.y);
                ffma2(acc2, wreg[32 + 4 * u + 2], hv1.x);
                ffma2(acc2, wreg[32 + 4 * u + 3], hv1.y);
            } else {
                uint4 wv2 = wsp[(4 + (u - 2)) * 512];
                ffma2(acc2, bf2pair(wv2.x), hv0.x);
                ffma2(acc2, bf2pair(wv2.y), hv0.y);
                ffma2(acc2, bf2pair(wv2.z), hv1.x);
                ffma2(acc2, bf2pair(wv2.w), hv1.y);
            }
            ffma2(acc3, bf2pair(wv.x), hv0.x);
            ffma2(acc3, bf2pair(wv.y), hv0.y);
            ffma2(acc3, bf2pair(wv.z), hv1.x);
            ffma2(acc3, bf2pair(wv.w), hv1.y);
        }

        float p0, p1, p2, p3, lo, hi;
        unpack2(acc0, lo, hi); p0 = lo + hi;
        unpack2(acc1, lo, hi); p1 = lo + hi;
        unpack2(acc2, lo, hi); p2 = lo + hi;
        unpack2(acc3, lo, hi); p3 = lo + hi;

        float s0 = p0 + __shfl_xor_sync(0xffffffffu, p1, 1);
        float s1 = p2 + __shfl_xor_sync(0xffffffffu, p3, 1);
        float z  = s0 + __shfl_xor_sync(0xffffffffu, s1, 2);

        float a = fmaf(sc, tanhaf(sc * z), scb);

        float gi_ = __shfl_sync(0xffffffffu, a, 0, 4);
        float gf_ = __shfl_sync(0xffffffffu, a, 1, 4);
        float gg_ = __shfl_sync(0xffffffffu, a, 2, 4);
        float go_ = __shfl_sync(0xffffffffu, a, 3, 4);

        c = fmaf(gf_, c, gi_ * gg_);
        float h = go_ * tanhaf(c);
        if (hwriter) S->hsk[(t + 1) & 1][hwidx] = h;

        xgq = xg_nxt;
        __syncthreads();
    }

    if (tid < 256) {
        int cls = tid >> 7;
        int jj  = tid & 127;
        float hv = S->hsk[0][(jj >> 5) * 36 + (jj & 31)];
        S->hred[tid] = hv * W_fc[cls * HID + jj];
    }
    __syncthreads();
    if (tid < 2) {
        float s = b_fc[tid];
#pragma unroll 8
        for (int jj = 0; jj < HID; jj++) s += S->hred[tid * HID + jj];
        out[b * 2 + tid] = s;
    }
}

// =====================================================================
extern "C" void kernel_launch(void* const* d_in, const int* in_sizes, int n_in,
                              void* d_out, int out_size)
{
    const void*  x     = d_in[0];
    const float* emb   = (const float*)d_in[1];
    const float* W_ih  = (const float*)d_in[2];
    const float* W_hh  = (const float*)d_in[3];
    const float* b_ih  = (const float*)d_in[4];
    const float* b_hh  = (const float*)d_in[5];
    const float* W_fc  = (const float*)d_in[6];
    const float* b_fc  = (const float*)d_in[7];
    float* out = (float*)d_out;

    // resolve device-global addresses (host-side, graph-safe)
    __nv_bfloat16 *p_embh, *p_embl, *p_wih_h, *p_wih_l;
    cudaGetSymbolAddress((void**)&p_embh,  g_embh);
    cudaGetSymbolAddress((void**)&p_embl,  g_embl);
    cudaGetSymbolAddress((void**)&p_wih_h, g_wih_h);
    cudaGetSymbolAddress((void**)&p_wih_l, g_wih_l);

    // 0) one-shot fp32 -> bf16 hi/lo splits
    conv_split_kernel<<<1024, 256>>>(emb,  p_embh,  p_embl,  (VOCAB * EMBED) / 4);
    conv_split_kernel<<<128,  256>>>(W_ih, p_wih_h, p_wih_l, (G4 * EMBED) / 4);

    // 1) tensor-core table GEMM
    cudaFuncSetAttribute(table_wmma_kernel, cudaFuncAttributeMaxDynamicSharedMemorySize, TB_SMEM);
    dim3 tgrid((VOCAB + 127) / 128, G4 / 128);   // 393 x 4
    table_wmma_kernel<<<tgrid, 256, TB_SMEM>>>(b_ih, b_hh);

    // 2) recurrence
    const int smem_bytes = (int)sizeof(LstmSmem);
    cudaFuncSetAttribute(lstm_kernel, cudaFuncAttributeMaxDynamicSharedMemorySize, smem_bytes);
    lstm_kernel<<<BATCH, 512, smem_bytes>>>(x, W_hh, W_fc, b_fc, out);
}